// round 15
// baseline (speedup 1.0000x reference)
#include <cuda_runtime.h>
#include <cuda_bf16.h>
#include <cstdint>

#define NCARDS 50000
#define NJ 49999
#define B 1024
#define NTOT4 204795904u       // B*NJ*4 bytes (fits u32)
#define JC 38
#define CHUNK 1344
#define NJ_PAD (JC*CHUNK)      // 51072
#define TILES 21
#define NCTA 608               // 38*16
#define LOG2E 1.4426950408889634f
#define KL_EPS 1e-7f
#define LG2_EPS -23.253496664211536f

// smem layout (bytes): E0[9216] E1[9216] ADJ0[17408] ADJ1[17408] = 53248
#define ES_STRIDE 144
#define ES_BYTES  9216
#define ADJ_STRIDE 68
#define ADJ_BYTES (64*ADJ_STRIDE*4)
#define ADJ_OFF   (2*ES_BYTES)
#define SMEM_G (ADJ_OFF + 2*ADJ_BYTES)   // 53248

// ---------------- device scratch ----------------
__device__ __nv_bfloat16 g_eB[(size_t)NJ_PAD*64];
__device__ __nv_bfloat16 g_aBF[B*64];
__device__ float    g_acc[B*4];
__device__ unsigned g_minL[B];
__device__ float    g_cross[B], g_lse2[B];
__device__ int      g_flag[B];
__device__ unsigned g_ctr;

// ---------------- helpers ----------------
__device__ __forceinline__ float ex2f_(float x){ float r; asm("ex2.approx.f32 %0, %1;" : "=f"(r) : "f"(x)); return r; }
__device__ __forceinline__ float lg2f_(float x){ float r; asm("lg2.approx.f32 %0, %1;" : "=f"(r) : "f"(x)); return r; }
__device__ __forceinline__ uint32_t smem_u32(const void* p){
    uint32_t a; asm("{ .reg .u64 t; cvta.to.shared.u64 t, %1; cvt.u32.u64 %0, t; }" : "=r"(a) : "l"(p)); return a; }
__device__ __forceinline__ unsigned ford(float f){
    int i = __float_as_int(f);
    return (i >= 0) ? ((unsigned)i | 0x80000000u) : ~(unsigned)i;
}
__device__ __forceinline__ float forddec(unsigned u){
    int i = (u & 0x80000000u) ? (int)(u & 0x7FFFFFFFu) : ~(int)u;
    return __int_as_float(i);
}
__device__ __forceinline__ void mma16816(float* c, const uint32_t* a, uint32_t b0, uint32_t b1){
    asm volatile("mma.sync.aligned.m16n8k16.row.col.f32.bf16.bf16.f32 "
        "{%0,%1,%2,%3}, {%4,%5,%6,%7}, {%8,%9}, {%0,%1,%2,%3};"
        : "+f"(c[0]), "+f"(c[1]), "+f"(c[2]), "+f"(c[3])
        : "r"(a[0]), "r"(a[1]), "r"(a[2]), "r"(a[3]), "r"(b0), "r"(b1));
}
#define LDM4(r0,r1,r2,r3,addr) \
    asm volatile("ldmatrix.sync.aligned.m8n8.x4.shared.b16 {%0,%1,%2,%3}, [%4];" \
        : "=r"(r0), "=r"(r1), "=r"(r2), "=r"(r3) : "r"(addr))

__device__ __forceinline__ void upd(float L, float y, float& z, float& t1, float& t2, float& t3, float& mn){
    y = fmaxf(y, KL_EPS);
    z += ex2f_(L);
    t1 = fmaf(y, L, t1);
    t2 += y;
    t3 = fmaf(y, lg2f_(y), t3);
    mn = fminf(mn, L);
}

// ---------------- kernel 0: normalize E[1:], 4 rows/warp ----------------
__global__ void k_enorm(const float* __restrict__ emb){
    int wid = threadIdx.x>>5, lane = threadIdx.x&31;
    int jb = (blockIdx.x*8 + wid)*4;
    float2 v[4]; float s[4];
#pragma unroll
    for(int r=0;r<4;r++){
        int j = jb + r;
        v[r] = make_float2(0.f, 0.f);
        if (j < NJ) v[r] = ((const float2*)emb)[(size_t)(j+1)*32 + lane];
        s[r] = v[r].x*v[r].x + v[r].y*v[r].y;
    }
#pragma unroll
    for(int o=16;o;o>>=1){
#pragma unroll
        for(int r=0;r<4;r++) s[r] += __shfl_xor_sync(0xffffffffu, s[r], o);
    }
#pragma unroll
    for(int r=0;r<4;r++){
        int j = jb + r;
        if (j < NJ_PAD){
            float inv = rsqrtf(fmaxf(s[r], 1e-12f));
            __nv_bfloat162 o2;
            o2.x = __float2bfloat16_rn(v[r].x*inv);
            o2.y = __float2bfloat16_rn(v[r].y*inv);
            ((__nv_bfloat162*)g_eB)[(size_t)j*32 + lane] = o2;
        }
    }
}

// ---------------- kernel 1: gather + MLP + l2norm, fold t*log2e ----------------
__global__ void __launch_bounds__(256) k_mlp(const int* __restrict__ cards, const float* __restrict__ emb,
        const float* __restrict__ W1, const float* __restrict__ b1,
        const float* __restrict__ W2, const float* __restrict__ b2,
        const float* __restrict__ temp){
    extern __shared__ float dyn[];
    float* sW1 = dyn;
    float* sW2 = dyn + 16384;
    float* se  = dyn + 32768;
    float* sh  = dyn + 33280;
    float* so  = dyn + 35328;
    float* ssc = dyn + 35840;
    int t = threadIdx.x;
    int b0 = blockIdx.x*8;
    const float4* W1v = (const float4*)W1; float4* s1v = (float4*)sW1;
    const float4* W2v = (const float4*)W2; float4* s2v = (float4*)sW2;
#pragma unroll
    for(int i=0;i<16;i++) s1v[t + i*256] = W1v[t + i*256];
#pragma unroll
    for(int i=0;i<16;i++) s2v[t + i*256] = W2v[t + i*256];
#pragma unroll
    for(int i=0;i<2;i++){ int idx = t + i*256; int bi = idx>>6, k = idx&63;
        se[idx] = emb[(size_t)cards[b0+bi]*64 + k]; }
    __syncthreads();
    float bb1 = b1[t];
#pragma unroll
    for(int bi=0;bi<8;bi++){
        float h = bb1;
#pragma unroll
        for(int k=0;k<64;k++) h = fmaf(se[bi*64+k], sW1[k*256+t], h);
        sh[bi*256+t] = fmaxf(h, 0.f);
    }
    __syncthreads();
    int d = t&63, q = t>>6;
    float bb2 = b2[d];
#pragma unroll
    for(int r=0;r<2;r++){
        int bi = q*2 + r;
        float o = bb2;
#pragma unroll 8
        for(int j=0;j<256;j++) o = fmaf(sh[bi*256+j], sW2[j*64+d], o);
        so[bi*64+d] = o;
    }
    __syncthreads();
    if (t < 8){
        float s = 0.f;
#pragma unroll
        for(int dd=0;dd<64;dd++){ float v = so[t*64+dd]; s = fmaf(v, v, s); }
        ssc[t] = temp[0]*LOG2E*rsqrtf(fmaxf(s, 1e-12f));
    }
    __syncthreads();
#pragma unroll
    for(int i=0;i<2;i++){ int idx = t + i*256; int bi = idx>>6;
        g_aBF[(size_t)b0*64 + idx] = __float2bfloat16_rn(so[idx]*ssc[bi]); }
}

// ---------------- kernel 2: init ----------------
__global__ void k_init(){
    int i = blockIdx.x*256 + threadIdx.x;   // 16x256 = 4096
    g_acc[i] = 0.f;
    if (i < B){ g_minL[i] = 0xFFFFFFFFu; g_flag[i] = 0; }
    if (i == 0) g_ctr = 0u;
}

// ---------------- staging: minimal live state (2 advancing regs) ----------------
// E: thread stages 2 chunks at offE, offE+4096 -> dstE, dstE+4608.
// adj: thread owns row=tid>>2, chunks ch=(tid&3)+4i (i<4), plus ch=16 if (tid&3)==0.
//      byte offsets are offA + i*64 (+256 for the fifth). All 16B cp.async.
__device__ __forceinline__ void stage_issue(uint32_t offE, uint32_t offA, int buf,
                                            uint32_t smbase, const char* __restrict__ adjB,
                                            uint32_t dstE, uint32_t dstA, bool fifth){
    uint32_t eb = smbase + buf*ES_BYTES;
    const char* eB = (const char*)g_eB;
    asm volatile("cp.async.cg.shared.global [%0], [%1], 16;" :: "r"(eb + dstE),        "l"(eB + offE));
    asm volatile("cp.async.cg.shared.global [%0], [%1], 16;" :: "r"(eb + dstE + 4608), "l"(eB + offE + 4096));
    uint32_t ab = smbase + ADJ_OFF + buf*ADJ_BYTES + dstA;
#pragma unroll
    for(int i=0;i<4;i++){
        uint32_t o = offA + i*64u;
        uint32_t d = ab + i*64u;
        if (o + 16 <= NTOT4){
            asm volatile("cp.async.cg.shared.global [%0], [%1], 16;" :: "r"(d), "l"(adjB + o));
        } else {
#pragma unroll
            for(int e=0;e<4;e++){
                float v = 0.f;
                if (o + e*4 + 4 <= NTOT4) v = __ldcs((const float*)(adjB + o + e*4));
                asm volatile("st.shared.f32 [%0], %1;" :: "r"(d + e*4), "f"(v));
            }
        }
    }
    if (fifth){
        uint32_t o = offA + 256u;
        uint32_t d = ab + 256u;
        if (o + 16 <= NTOT4){
            asm volatile("cp.async.cg.shared.global [%0], [%1], 16;" :: "r"(d), "l"(adjB + o));
        } else {
#pragma unroll
            for(int e=0;e<4;e++){
                float v = 0.f;
                if (o + e*4 + 4 <= NTOT4) v = __ldcs((const float*)(adjB + o + e*4));
                asm volatile("st.shared.f32 [%0], %1;" :: "r"(d + e*4), "f"(v));
            }
        }
    }
    asm volatile("cp.async.commit_group;" ::: "memory");
}

// ---------------- kernel 3: HMMA GEMM + fused stats + last-CTA finalize ----------------
// grid (38,16), 256 thr, 4 CTAs/SM. M-tile 64, N-tile 64, warp grid 4m x 2n.
__global__ void __launch_bounds__(256, 4) k_gemm9(const float* __restrict__ adj,
                                                  const float* __restrict__ temp,
                                                  float* __restrict__ out){
    extern __shared__ __align__(16) char sm9[];
    const uint32_t smbase = smem_u32(sm9);
    int tid = threadIdx.x;
    int wid = tid>>5, lane = tid&31, g = lane>>2, tg = lane&3;
    int wr = wid&3, wc = wid>>2;
    int jc = blockIdx.x, rt = blockIdx.y;
    int jstart = jc*CHUNK;

    int r0l = wr*16 + g;
    int r0g = rt*64 + r0l;

    uint32_t A[4][4];
    {
        const uint32_t* a0 = (const uint32_t*)(g_aBF + (size_t)r0g*64);
        const uint32_t* a1 = (const uint32_t*)(g_aBF + (size_t)(r0g+8)*64);
#pragma unroll
        for(int kt=0;kt<4;kt++){
            A[kt][0]=a0[kt*8+tg];   A[kt][1]=a1[kt*8+tg];
            A[kt][2]=a0[kt*8+tg+4]; A[kt][3]=a1[kt*8+tg+4];
        }
    }
    const int ash = (int)(((size_t)r0g*NJ + (unsigned)jstart) & 3);
    const uint32_t lmo = (uint32_t)((wc*32 + (lane&7))*ES_STRIDE + (lane>>3)*16);
    const char* adjB = (const char*)adj;

    // staging constants (recomputed cheaply) + 2 advancing offsets
    const uint32_t dstE = (uint32_t)(tid>>3)*ES_STRIDE + (uint32_t)(tid&7)*16u;
    const uint32_t dstA = (uint32_t)(tid>>2)*(ADJ_STRIDE*4) + (uint32_t)(tid&3)*16u;
    const bool fifth = (tid&3) == 0;
    uint32_t offE = (uint32_t)(jstart + (tid>>3))*128u + (uint32_t)(tid&7)*16u;
    uint32_t offA;
    {
        size_t base = (size_t)(rt*64 + (tid>>2))*NJ + (unsigned)jstart;     // elements
        offA = (uint32_t)((base & ~(size_t)3)*4) + (uint32_t)(tid&3)*16u;
    }

    float Z[2]={0.f,0.f}, T1[2]={0.f,0.f}, T2[2]={0.f,0.f}, T3[2]={0.f,0.f}, MN[2]={1e30f,1e30f};

    stage_issue(offE, offA, 0, smbase, adjB, dstE, dstA, fifth);
    offE += 8192; offA += 256;

    if (jc != JC-1){
        // ======== fast path: 21 full tiles ========
#pragma unroll 1
        for(int t=0;t<TILES;t++){
            if (t < TILES-1){
                stage_issue(offE, offA, (t+1)&1, smbase, adjB, dstE, dstA, fifth);
                offE += 8192; offA += 256;
                asm volatile("cp.async.wait_group 1;" ::: "memory");
            } else {
                asm volatile("cp.async.wait_group 0;" ::: "memory");
            }
            __syncthreads();

            uint32_t esb = smbase + (t&1)*ES_BYTES + lmo;
            const float* srow0 = (const float*)(sm9 + ADJ_OFF + (t&1)*ADJ_BYTES) + r0l*ADJ_STRIDE + ash;
            const float* srow1 = srow0 + 8*ADJ_STRIDE;

            float acc[4][4];
#pragma unroll
            for(int nt=0;nt<4;nt++){ acc[nt][0]=0.f; acc[nt][1]=0.f; acc[nt][2]=0.f; acc[nt][3]=0.f; }
#pragma unroll
            for(int nt=0;nt<4;nt++){
                uint32_t ad = esb + nt*(8*ES_STRIDE);
                uint32_t b00,b01,b10,b11,b20,b21,b30,b31;
                LDM4(b00,b01,b10,b11, ad);
                LDM4(b20,b21,b30,b31, ad + 64);
                mma16816(acc[nt], A[0], b00, b01);
                mma16816(acc[nt], A[1], b10, b11);
                mma16816(acc[nt], A[2], b20, b21);
                mma16816(acc[nt], A[3], b30, b31);
            }
#pragma unroll
            for(int nt=0;nt<4;nt++){
                int c = wc*32 + nt*8 + tg*2;
                upd(acc[nt][0], srow0[c],   Z[0],T1[0],T2[0],T3[0],MN[0]);
                upd(acc[nt][1], srow0[c+1], Z[0],T1[0],T2[0],T3[0],MN[0]);
                upd(acc[nt][2], srow1[c],   Z[1],T1[1],T2[1],T3[1],MN[1]);
                upd(acc[nt][3], srow1[c+1], Z[1],T1[1],T2[1],T3[1],MN[1]);
            }
            __syncthreads();
        }
    } else {
        // ======== general path: last chunk (271 cols, 5 tiles) ========
        int nvalid = NJ - jstart;
        int ntiles = (nvalid + 63)>>6;
#pragma unroll 1
        for(int t=0;t<ntiles;t++){
            int j0 = jstart + (t<<6);
            int jv = NJ - j0; if (jv > 64) jv = 64;
            if (t < ntiles-1){
                stage_issue(offE, offA, (t+1)&1, smbase, adjB, dstE, dstA, fifth);
                offE += 8192; offA += 256;
                asm volatile("cp.async.wait_group 1;" ::: "memory");
            } else {
                asm volatile("cp.async.wait_group 0;" ::: "memory");
            }
            __syncthreads();

            uint32_t esb = smbase + (t&1)*ES_BYTES + lmo;
            const float* srow0 = (const float*)(sm9 + ADJ_OFF + (t&1)*ADJ_BYTES) + r0l*ADJ_STRIDE + ash;
            const float* srow1 = srow0 + 8*ADJ_STRIDE;

            float acc[4][4];
#pragma unroll
            for(int nt=0;nt<4;nt++){ acc[nt][0]=0.f; acc[nt][1]=0.f; acc[nt][2]=0.f; acc[nt][3]=0.f; }
#pragma unroll
            for(int nt=0;nt<4;nt++){
                uint32_t ad = esb + nt*(8*ES_STRIDE);
                uint32_t b00,b01,b10,b11,b20,b21,b30,b31;
                LDM4(b00,b01,b10,b11, ad);
                LDM4(b20,b21,b30,b31, ad + 64);
                mma16816(acc[nt], A[0], b00, b01);
                mma16816(acc[nt], A[1], b10, b11);
                mma16816(acc[nt], A[2], b20, b21);
                mma16816(acc[nt], A[3], b30, b31);
            }
#pragma unroll
            for(int nt=0;nt<4;nt++){
                int c = wc*32 + nt*8 + tg*2;
                if (c < jv){
                    upd(acc[nt][0], srow0[c], Z[0],T1[0],T2[0],T3[0],MN[0]);
                    upd(acc[nt][2], srow1[c], Z[1],T1[1],T2[1],T3[1],MN[1]);
                    if (c + 1 < jv){
                        upd(acc[nt][1], srow0[c+1], Z[0],T1[0],T2[0],T3[0],MN[0]);
                        upd(acc[nt][3], srow1[c+1], Z[1],T1[1],T2[1],T3[1],MN[1]);
                    }
                }
            }
            __syncthreads();
        }
    }

    // reduce over tg lanes, atomic merge
#pragma unroll
    for(int r=0;r<2;r++){
#pragma unroll
        for(int off=1; off<4; off<<=1){
            Z[r]  += __shfl_xor_sync(0xffffffffu, Z[r],  off);
            T1[r] += __shfl_xor_sync(0xffffffffu, T1[r], off);
            T2[r] += __shfl_xor_sync(0xffffffffu, T2[r], off);
            T3[r] += __shfl_xor_sync(0xffffffffu, T3[r], off);
            MN[r]  = fminf(MN[r], __shfl_xor_sync(0xffffffffu, MN[r], off));
        }
    }
    if (tg == 0){
#pragma unroll
        for(int r=0;r<2;r++){
            int row = r0g + r*8;
            atomicAdd(&g_acc[row*4+0], Z[r]);
            atomicAdd(&g_acc[row*4+1], T1[r]);
            atomicAdd(&g_acc[row*4+2], T2[r]);
            atomicAdd(&g_acc[row*4+3], T3[r]);
            atomicMin(&g_minL[row], ford(MN[r]));
        }
    }

    // ---- last CTA finalizes ----
    __threadfence();
    __shared__ unsigned s_last;
    if (tid == 0) s_last = (atomicAdd(&g_ctr, 1u) == NCTA-1) ? 1u : 0u;
    __syncthreads();
    if (!s_last) return;

    float* red = (float*)sm9;
    float T = temp[0];
    float local = 0.f;
#pragma unroll
    for(int i=0;i<4;i++){
        int b = tid + i*256;
        float Zb, T1b, T2b, T3b; unsigned mu;
        asm("ld.global.cg.f32 %0, [%1];" : "=f"(Zb)  : "l"(&g_acc[b*4+0]));
        asm("ld.global.cg.f32 %0, [%1];" : "=f"(T1b) : "l"(&g_acc[b*4+1]));
        asm("ld.global.cg.f32 %0, [%1];" : "=f"(T2b) : "l"(&g_acc[b*4+2]));
        asm("ld.global.cg.f32 %0, [%1];" : "=f"(T3b) : "l"(&g_acc[b*4+3]));
        asm("ld.global.cg.u32 %0, [%1];" : "=r"(mu)  : "l"(&g_minL[b]));
        float lse2 = lg2f_(Zb);
        float cross = T1b - lse2*T2b;
        g_lse2[b] = lse2;
        g_cross[b] = cross;
        if (forddec(mu) - lse2 < LG2_EPS + 0.02f) g_flag[b] = 1;
        local += T3b - cross;
    }
    red[tid] = local;
    __syncthreads();
    for(int s=128;s;s>>=1){ if (tid < s) red[tid] += red[tid+s]; __syncthreads(); }
    if (tid == 0) out[0] = red[0]*(1.0f/(float)B) + T*T*0.01f;
}

// ---------------- kernel 4: exact clipped fixup (cold, normally no-op) ----------------
__global__ void k_fixup(const float* __restrict__ adj, float* __restrict__ out){
    __shared__ int flags[128];
    __shared__ int any;
    __shared__ float a[64];
    __shared__ float red[256];
    int b0 = blockIdx.x*128;
    int t = threadIdx.x;
    if (t == 0) any = 0;
    __syncthreads();
    if (t < 128){ int f = g_flag[b0+t]; flags[t] = f; if (f) any = 1; }
    __syncthreads();
    if (!any) return;
    for(int r=0;r<128;r++){
        if (!flags[r]) continue;
        int b = b0 + r;
        if (t < 64) a[t] = __bfloat162float(g_aBF[b*64 + t]);
        __syncthreads();
        float lse2 = g_lse2[b];
        float cr = 0.f;
        for(int j=t; j<NJ; j+=256){
            float L = 0.f;
#pragma unroll
            for(int k=0;k<64;k++) L = fmaf(a[k], __bfloat162float(g_eB[(size_t)j*64 + k]), L);
            float y = fmaxf(adj[(size_t)b*NJ + j], KL_EPS);
            cr = fmaf(y, fmaxf(L - lse2, LG2_EPS), cr);
        }
        red[t] = cr; __syncthreads();
        for(int s=128;s;s>>=1){ if (t < s) red[t] += red[t+s]; __syncthreads(); }
        if (t == 0) atomicAdd(out, (g_cross[b] - red[0])*(1.0f/(float)B));
        __syncthreads();
    }
}

// ---------------- launch ----------------
extern "C" void kernel_launch(void* const* d_in, const int* in_sizes, int n_in,
                              void* d_out, int out_size){
    const int*   cards = (const int*)  d_in[0];
    const float* adj   = (const float*)d_in[1];
    const float* emb   = (const float*)d_in[2];
    const float* W1    = (const float*)d_in[3];
    const float* b1    = (const float*)d_in[4];
    const float* W2    = (const float*)d_in[5];
    const float* b2    = (const float*)d_in[6];
    const float* temp  = (const float*)d_in[7];

    cudaFuncSetAttribute(k_mlp,   cudaFuncAttributeMaxDynamicSharedMemorySize, 143392);
    cudaFuncSetAttribute(k_gemm9, cudaFuncAttributeMaxDynamicSharedMemorySize, SMEM_G);

    k_enorm<<<1596, 256>>>(emb);                                   // idx 0
    k_mlp<<<128, 256, 143392>>>(cards, emb, W1, b1, W2, b2, temp); // idx 1
    k_init<<<16, 256>>>();                                         // idx 2
    k_gemm9<<<dim3(JC, 16), 256, SMEM_G>>>(adj, temp, (float*)d_out); // idx 3 (ncu target)
    k_fixup<<<8, 256>>>(adj, (float*)d_out);                       // idx 4
}

// round 16
// speedup vs baseline: 1.1026x; 1.1026x over previous
#include <cuda_runtime.h>
#include <cuda_bf16.h>
#include <cstdint>

#define NCARDS 50000
#define NJ 49999
#define B 1024
#define NTOT4 204795904u       // B*NJ*4 bytes (fits u32)
#define JC 38
#define CHUNK 1344
#define NJ_PAD (JC*CHUNK)      // 51072
#define TILES 21
#define NCTA 608               // 38*16
#define LOG2E 1.4426950408889634f
#define KL_EPS 1e-7f
#define LG2_EPS -23.253496664211536f

// smem layout (bytes): E0[9216] E1[9216] ADJ0[17408] ADJ1[17408] = 53248
#define ES_STRIDE 144
#define ES_BYTES  9216
#define ADJ_STRIDE 68
#define ADJ_BYTES (64*ADJ_STRIDE*4)
#define ADJ_OFF   (2*ES_BYTES)
#define SMEM_G (ADJ_OFF + 2*ADJ_BYTES)   // 53248

// ---------------- device scratch ----------------
__device__ __nv_bfloat16 g_eB[(size_t)NJ_PAD*64];
__device__ __nv_bfloat16 g_aBF[B*64];
__device__ float    g_acc[B*4];
__device__ unsigned g_minL[B];
__device__ float    g_cross[B], g_lse2[B];
__device__ int      g_flag[B];
__device__ unsigned g_ctr;

// ---------------- helpers ----------------
__device__ __forceinline__ float ex2f_(float x){ float r; asm("ex2.approx.f32 %0, %1;" : "=f"(r) : "f"(x)); return r; }
__device__ __forceinline__ float lg2f_(float x){ float r; asm("lg2.approx.f32 %0, %1;" : "=f"(r) : "f"(x)); return r; }
__device__ __forceinline__ uint32_t smem_u32(const void* p){
    uint32_t a; asm("{ .reg .u64 t; cvta.to.shared.u64 t, %1; cvt.u32.u64 %0, t; }" : "=r"(a) : "l"(p)); return a; }
__device__ __forceinline__ unsigned ford(float f){
    int i = __float_as_int(f);
    return (i >= 0) ? ((unsigned)i | 0x80000000u) : ~(unsigned)i;
}
__device__ __forceinline__ float forddec(unsigned u){
    int i = (u & 0x80000000u) ? (int)(u & 0x7FFFFFFFu) : ~(int)u;
    return __int_as_float(i);
}
__device__ __forceinline__ void mma16816(float* c, const uint32_t* a, uint32_t b0, uint32_t b1){
    asm volatile("mma.sync.aligned.m16n8k16.row.col.f32.bf16.bf16.f32 "
        "{%0,%1,%2,%3}, {%4,%5,%6,%7}, {%8,%9}, {%0,%1,%2,%3};"
        : "+f"(c[0]), "+f"(c[1]), "+f"(c[2]), "+f"(c[3])
        : "r"(a[0]), "r"(a[1]), "r"(a[2]), "r"(a[3]), "r"(b0), "r"(b1));
}
#define LDM4(r0,r1,r2,r3,addr) \
    asm volatile("ldmatrix.sync.aligned.m8n8.x4.shared.b16 {%0,%1,%2,%3}, [%4];" \
        : "=r"(r0), "=r"(r1), "=r"(r2), "=r"(r3) : "r"(addr))

__device__ __forceinline__ void upd(float L, float y, float& z, float& t1, float& t2, float& t3, float& mn){
    y = fmaxf(y, KL_EPS);
    z += ex2f_(L);
    t1 = fmaf(y, L, t1);
    t2 += y;
    t3 = fmaf(y, lg2f_(y), t3);
    mn = fminf(mn, L);
}

// ---------------- kernel 0: normalize E[1:], 4 rows/warp ----------------
__global__ void k_enorm(const float* __restrict__ emb){
    int wid = threadIdx.x>>5, lane = threadIdx.x&31;
    int jb = (blockIdx.x*8 + wid)*4;
    float2 v[4]; float s[4];
#pragma unroll
    for(int r=0;r<4;r++){
        int j = jb + r;
        v[r] = make_float2(0.f, 0.f);
        if (j < NJ) v[r] = ((const float2*)emb)[(size_t)(j+1)*32 + lane];
        s[r] = v[r].x*v[r].x + v[r].y*v[r].y;
    }
#pragma unroll
    for(int o=16;o;o>>=1){
#pragma unroll
        for(int r=0;r<4;r++) s[r] += __shfl_xor_sync(0xffffffffu, s[r], o);
    }
#pragma unroll
    for(int r=0;r<4;r++){
        int j = jb + r;
        if (j < NJ_PAD){
            float inv = rsqrtf(fmaxf(s[r], 1e-12f));
            __nv_bfloat162 o2;
            o2.x = __float2bfloat16_rn(v[r].x*inv);
            o2.y = __float2bfloat16_rn(v[r].y*inv);
            ((__nv_bfloat162*)g_eB)[(size_t)j*32 + lane] = o2;
        }
    }
}

// ---------------- kernel 1: gather + MLP + l2norm, fold t*log2e ----------------
__global__ void __launch_bounds__(256) k_mlp(const int* __restrict__ cards, const float* __restrict__ emb,
        const float* __restrict__ W1, const float* __restrict__ b1,
        const float* __restrict__ W2, const float* __restrict__ b2,
        const float* __restrict__ temp){
    extern __shared__ float dyn[];
    float* sW1 = dyn;
    float* sW2 = dyn + 16384;
    float* se  = dyn + 32768;
    float* sh  = dyn + 33280;
    float* so  = dyn + 35328;
    float* ssc = dyn + 35840;
    int t = threadIdx.x;
    int b0 = blockIdx.x*8;
    const float4* W1v = (const float4*)W1; float4* s1v = (float4*)sW1;
    const float4* W2v = (const float4*)W2; float4* s2v = (float4*)sW2;
#pragma unroll
    for(int i=0;i<16;i++) s1v[t + i*256] = W1v[t + i*256];
#pragma unroll
    for(int i=0;i<16;i++) s2v[t + i*256] = W2v[t + i*256];
#pragma unroll
    for(int i=0;i<2;i++){ int idx = t + i*256; int bi = idx>>6, k = idx&63;
        se[idx] = emb[(size_t)cards[b0+bi]*64 + k]; }
    __syncthreads();
    float bb1 = b1[t];
#pragma unroll
    for(int bi=0;bi<8;bi++){
        float h = bb1;
#pragma unroll
        for(int k=0;k<64;k++) h = fmaf(se[bi*64+k], sW1[k*256+t], h);
        sh[bi*256+t] = fmaxf(h, 0.f);
    }
    __syncthreads();
    int d = t&63, q = t>>6;
    float bb2 = b2[d];
#pragma unroll
    for(int r=0;r<2;r++){
        int bi = q*2 + r;
        float o = bb2;
#pragma unroll 8
        for(int j=0;j<256;j++) o = fmaf(sh[bi*256+j], sW2[j*64+d], o);
        so[bi*64+d] = o;
    }
    __syncthreads();
    if (t < 8){
        float s = 0.f;
#pragma unroll
        for(int dd=0;dd<64;dd++){ float v = so[t*64+dd]; s = fmaf(v, v, s); }
        ssc[t] = temp[0]*LOG2E*rsqrtf(fmaxf(s, 1e-12f));
    }
    __syncthreads();
#pragma unroll
    for(int i=0;i<2;i++){ int idx = t + i*256; int bi = idx>>6;
        g_aBF[(size_t)b0*64 + idx] = __float2bfloat16_rn(so[idx]*ssc[bi]); }
}

// ---------------- kernel 2: init ----------------
__global__ void k_init(){
    int i = blockIdx.x*256 + threadIdx.x;   // 16x256 = 4096
    g_acc[i] = 0.f;
    if (i < B){ g_minL[i] = 0xFFFFFFFFu; g_flag[i] = 0; }
    if (i == 0) g_ctr = 0u;
}

// ---------------- staging state (per-thread, hoisted; R14 chunk-major layout) ----------------
struct Stage {
    uint32_t offE[2];      // byte offset into g_eB (advance +8192/tile)
    uint32_t dstE[2];      // smem offset (add buf base)
    uint32_t offA[5];      // byte offset into adj (advance +256/tile)
    uint32_t dstA[5];      // smem offset within ADJ region
    uint32_t nA;           // valid adj chunks (4 or 5)
};

__device__ __forceinline__ void stage_issue(Stage& st, int buf, uint32_t smbase,
                                            const char* __restrict__ adjB){
    uint32_t eb = smbase + buf*ES_BYTES;
    const char* eB = (const char*)g_eB;
#pragma unroll
    for(int i=0;i<2;i++){
        asm volatile("cp.async.cg.shared.global [%0], [%1], 16;"
                     :: "r"(eb + st.dstE[i]), "l"(eB + st.offE[i]));
        st.offE[i] += 8192;
    }
    uint32_t ab = smbase + ADJ_OFF + buf*ADJ_BYTES;
#pragma unroll
    for(int i=0;i<5;i++){
        if (i < (int)st.nA){
            uint32_t o = st.offA[i];
            uint32_t d = ab + st.dstA[i];
            if (o + 16 <= NTOT4){
                asm volatile("cp.async.cg.shared.global [%0], [%1], 16;"
                             :: "r"(d), "l"(adjB + o));
            } else {
#pragma unroll
                for(int e=0;e<4;e++){
                    float v = 0.f;
                    if (o + e*4 + 4 <= NTOT4) v = __ldcs((const float*)(adjB + o + e*4));
                    asm volatile("st.shared.f32 [%0], %1;" :: "r"(d + e*4), "f"(v));
                }
            }
            st.offA[i] += 256;
        }
    }
    asm volatile("cp.async.commit_group;" ::: "memory");
}

// ---------------- kernel 3: HMMA GEMM + fused stats + last-CTA finalize ----------------
// grid (38,16), 256 thr, 4 CTAs/SM. M-tile 64, N-tile 64, warp grid 4m x 2n.
// Epilogue restructured per-nt: acc live range 16 -> 4 regs; MN merged across row pair.
__global__ void __launch_bounds__(256, 4) k_gemm9(const float* __restrict__ adj,
                                                  const float* __restrict__ temp,
                                                  float* __restrict__ out){
    extern __shared__ __align__(16) char sm9[];
    const uint32_t smbase = smem_u32(sm9);
    int tid = threadIdx.x;
    int wid = tid>>5, lane = tid&31, g = lane>>2, tg = lane&3;
    int wr = wid&3, wc = wid>>2;
    int jc = blockIdx.x, rt = blockIdx.y;
    int jstart = jc*CHUNK;

    int r0l = wr*16 + g;
    int r0g = rt*64 + r0l;

    uint32_t A[4][4];
    {
        const uint32_t* a0 = (const uint32_t*)(g_aBF + (size_t)r0g*64);
        const uint32_t* a1 = (const uint32_t*)(g_aBF + (size_t)(r0g+8)*64);
#pragma unroll
        for(int kt=0;kt<4;kt++){
            A[kt][0]=a0[kt*8+tg];   A[kt][1]=a1[kt*8+tg];
            A[kt][2]=a0[kt*8+tg+4]; A[kt][3]=a1[kt*8+tg+4];
        }
    }
    const int ash = (int)(((size_t)r0g*NJ + (unsigned)jstart) & 3);
    const uint32_t lmo = (uint32_t)((wc*32 + (lane&7))*ES_STRIDE + (lane>>3)*16);
    const char* adjB = (const char*)adj;

    // hoisted staging offsets (R14 chunk-major: warp covers contiguous row segments)
    Stage st;
#pragma unroll
    for(int i=0;i<2;i++){
        int c = tid + i*256;
        int row = c>>3, seg = c&7;
        st.offE[i] = (uint32_t)(jstart + row)*128u + seg*16u;
        st.dstE[i] = (uint32_t)row*ES_STRIDE + seg*16u;
    }
    {
        int n = 0;
#pragma unroll
        for(int i=0;i<5;i++){
            int idx = tid + i*256;
            if (idx < 1088){
                int row = idx/17, ch = idx - row*17;
                size_t base = (size_t)(rt*64 + row)*NJ + (unsigned)jstart;   // elements
                st.offA[n] = (uint32_t)((base & ~(size_t)3)*4) + (uint32_t)ch*16u;
                st.dstA[n] = (uint32_t)row*(ADJ_STRIDE*4) + (uint32_t)ch*16u;
                n++;
            }
        }
        st.nA = (uint32_t)n;
    }

    float Z[2]={0.f,0.f}, T1[2]={0.f,0.f}, T2[2]={0.f,0.f}, T3[2]={0.f,0.f};
    float MN = 1e30f;   // merged min over both rows (conservative flag; fixup is exact)

    stage_issue(st, 0, smbase, adjB);

    if (jc != JC-1){
        // ======== fast path: 21 full tiles ========
#pragma unroll 1
        for(int t=0;t<TILES;t++){
            if (t < TILES-1){
                stage_issue(st, (t+1)&1, smbase, adjB);
                asm volatile("cp.async.wait_group 1;" ::: "memory");
            } else {
                asm volatile("cp.async.wait_group 0;" ::: "memory");
            }
            __syncthreads();

            uint32_t esb = smbase + (t&1)*ES_BYTES + lmo;
            const float* srow0 = (const float*)(sm9 + ADJ_OFF + (t&1)*ADJ_BYTES) + r0l*ADJ_STRIDE + ash;
            const float* srow1 = srow0 + 8*ADJ_STRIDE;

#pragma unroll
            for(int nt=0;nt<4;nt++){
                float acc[4] = {0.f, 0.f, 0.f, 0.f};
                uint32_t ad = esb + nt*(8*ES_STRIDE);
                uint32_t b00,b01,b10,b11,b20,b21,b30,b31;
                LDM4(b00,b01,b10,b11, ad);
                LDM4(b20,b21,b30,b31, ad + 64);
                mma16816(acc, A[0], b00, b01);
                mma16816(acc, A[1], b10, b11);
                mma16816(acc, A[2], b20, b21);
                mma16816(acc, A[3], b30, b31);
                int c = wc*32 + nt*8 + tg*2;
                upd(acc[0], srow0[c],   Z[0],T1[0],T2[0],T3[0],MN);
                upd(acc[1], srow0[c+1], Z[0],T1[0],T2[0],T3[0],MN);
                upd(acc[2], srow1[c],   Z[1],T1[1],T2[1],T3[1],MN);
                upd(acc[3], srow1[c+1], Z[1],T1[1],T2[1],T3[1],MN);
            }
            __syncthreads();
        }
    } else {
        // ======== general path: last chunk (271 cols, 5 tiles) ========
        int nvalid = NJ - jstart;
        int ntiles = (nvalid + 63)>>6;
#pragma unroll 1
        for(int t=0;t<ntiles;t++){
            int j0 = jstart + (t<<6);
            int jv = NJ - j0; if (jv > 64) jv = 64;
            if (t < ntiles-1){
                stage_issue(st, (t+1)&1, smbase, adjB);
                asm volatile("cp.async.wait_group 1;" ::: "memory");
            } else {
                asm volatile("cp.async.wait_group 0;" ::: "memory");
            }
            __syncthreads();

            uint32_t esb = smbase + (t&1)*ES_BYTES + lmo;
            const float* srow0 = (const float*)(sm9 + ADJ_OFF + (t&1)*ADJ_BYTES) + r0l*ADJ_STRIDE + ash;
            const float* srow1 = srow0 + 8*ADJ_STRIDE;

#pragma unroll
            for(int nt=0;nt<4;nt++){
                float acc[4] = {0.f, 0.f, 0.f, 0.f};
                uint32_t ad = esb + nt*(8*ES_STRIDE);
                uint32_t b00,b01,b10,b11,b20,b21,b30,b31;
                LDM4(b00,b01,b10,b11, ad);
                LDM4(b20,b21,b30,b31, ad + 64);
                mma16816(acc, A[0], b00, b01);
                mma16816(acc, A[1], b10, b11);
                mma16816(acc, A[2], b20, b21);
                mma16816(acc, A[3], b30, b31);
                int c = wc*32 + nt*8 + tg*2;
                if (c < jv){
                    upd(acc[0], srow0[c], Z[0],T1[0],T2[0],T3[0],MN);
                    upd(acc[2], srow1[c], Z[1],T1[1],T2[1],T3[1],MN);
                    if (c + 1 < jv){
                        upd(acc[1], srow0[c+1], Z[0],T1[0],T2[0],T3[0],MN);
                        upd(acc[3], srow1[c+1], Z[1],T1[1],T2[1],T3[1],MN);
                    }
                }
            }
            __syncthreads();
        }
    }

    // reduce over tg lanes, atomic merge
#pragma unroll
    for(int r=0;r<2;r++){
#pragma unroll
        for(int off=1; off<4; off<<=1){
            Z[r]  += __shfl_xor_sync(0xffffffffu, Z[r],  off);
            T1[r] += __shfl_xor_sync(0xffffffffu, T1[r], off);
            T2[r] += __shfl_xor_sync(0xffffffffu, T2[r], off);
            T3[r] += __shfl_xor_sync(0xffffffffu, T3[r], off);
        }
    }
#pragma unroll
    for(int off=1; off<4; off<<=1)
        MN = fminf(MN, __shfl_xor_sync(0xffffffffu, MN, off));
    if (tg == 0){
        unsigned mnu = ford(MN);
#pragma unroll
        for(int r=0;r<2;r++){
            int row = r0g + r*8;
            atomicAdd(&g_acc[row*4+0], Z[r]);
            atomicAdd(&g_acc[row*4+1], T1[r]);
            atomicAdd(&g_acc[row*4+2], T2[r]);
            atomicAdd(&g_acc[row*4+3], T3[r]);
            atomicMin(&g_minL[row], mnu);
        }
    }

    // ---- last CTA finalizes ----
    __threadfence();
    __shared__ unsigned s_last;
    if (tid == 0) s_last = (atomicAdd(&g_ctr, 1u) == NCTA-1) ? 1u : 0u;
    __syncthreads();
    if (!s_last) return;

    float* red = (float*)sm9;
    float T = temp[0];
    float local = 0.f;
#pragma unroll
    for(int i=0;i<4;i++){
        int b = tid + i*256;
        float Zb, T1b, T2b, T3b; unsigned mu;
        asm("ld.global.cg.f32 %0, [%1];" : "=f"(Zb)  : "l"(&g_acc[b*4+0]));
        asm("ld.global.cg.f32 %0, [%1];" : "=f"(T1b) : "l"(&g_acc[b*4+1]));
        asm("ld.global.cg.f32 %0, [%1];" : "=f"(T2b) : "l"(&g_acc[b*4+2]));
        asm("ld.global.cg.f32 %0, [%1];" : "=f"(T3b) : "l"(&g_acc[b*4+3]));
        asm("ld.global.cg.u32 %0, [%1];" : "=r"(mu)  : "l"(&g_minL[b]));
        float lse2 = lg2f_(Zb);
        float cross = T1b - lse2*T2b;
        g_lse2[b] = lse2;
        g_cross[b] = cross;
        if (forddec(mu) - lse2 < LG2_EPS + 0.02f) g_flag[b] = 1;
        local += T3b - cross;
    }
    red[tid] = local;
    __syncthreads();
    for(int s=128;s;s>>=1){ if (tid < s) red[tid] += red[tid+s]; __syncthreads(); }
    if (tid == 0) out[0] = red[0]*(1.0f/(float)B) + T*T*0.01f;
}

// ---------------- kernel 4: exact clipped fixup (cold, normally no-op) ----------------
__global__ void k_fixup(const float* __restrict__ adj, float* __restrict__ out){
    __shared__ int flags[128];
    __shared__ int any;
    __shared__ float a[64];
    __shared__ float red[256];
    int b0 = blockIdx.x*128;
    int t = threadIdx.x;
    if (t == 0) any = 0;
    __syncthreads();
    if (t < 128){ int f = g_flag[b0+t]; flags[t] = f; if (f) any = 1; }
    __syncthreads();
    if (!any) return;
    for(int r=0;r<128;r++){
        if (!flags[r]) continue;
        int b = b0 + r;
        if (t < 64) a[t] = __bfloat162float(g_aBF[b*64 + t]);
        __syncthreads();
        float lse2 = g_lse2[b];
        float cr = 0.f;
        for(int j=t; j<NJ; j+=256){
            float L = 0.f;
#pragma unroll
            for(int k=0;k<64;k++) L = fmaf(a[k], __bfloat162float(g_eB[(size_t)j*64 + k]), L);
            float y = fmaxf(adj[(size_t)b*NJ + j], KL_EPS);
            cr = fmaf(y, fmaxf(L - lse2, LG2_EPS), cr);
        }
        red[t] = cr; __syncthreads();
        for(int s=128;s;s>>=1){ if (t < s) red[t] += red[t+s]; __syncthreads(); }
        if (t == 0) atomicAdd(out, (g_cross[b] - red[0])*(1.0f/(float)B));
        __syncthreads();
    }
}

// ---------------- launch ----------------
extern "C" void kernel_launch(void* const* d_in, const int* in_sizes, int n_in,
                              void* d_out, int out_size){
    const int*   cards = (const int*)  d_in[0];
    const float* adj   = (const float*)d_in[1];
    const float* emb   = (const float*)d_in[2];
    const float* W1    = (const float*)d_in[3];
    const float* b1    = (const float*)d_in[4];
    const float* W2    = (const float*)d_in[5];
    const float* b2    = (const float*)d_in[6];
    const float* temp  = (const float*)d_in[7];

    cudaFuncSetAttribute(k_mlp,   cudaFuncAttributeMaxDynamicSharedMemorySize, 143392);
    cudaFuncSetAttribute(k_gemm9, cudaFuncAttributeMaxDynamicSharedMemorySize, SMEM_G);

    k_enorm<<<1596, 256>>>(emb);                                   // idx 0
    k_mlp<<<128, 256, 143392>>>(cards, emb, W1, b1, W2, b2, temp); // idx 1
    k_init<<<16, 256>>>();                                         // idx 2
    k_gemm9<<<dim3(JC, 16), 256, SMEM_G>>>(adj, temp, (float*)d_out); // idx 3 (ncu target)
    k_fixup<<<8, 256>>>(adj, (float*)d_out);                       // idx 4
}

// round 17
// speedup vs baseline: 1.1218x; 1.0175x over previous
#include <cuda_runtime.h>
#include <cuda_bf16.h>
#include <cstdint>

#define NCARDS 50000
#define NJ 49999
#define B 1024
#define NTOT4 204795904u       // B*NJ*4 bytes (fits u32)
#define JC 38
#define CHUNK 1344
#define NJ_PAD (JC*CHUNK)      // 51072
#define TILES 21
#define NCTA 608               // 38*16
#define LOG2E 1.4426950408889634f
#define KL_EPS 1e-7f
#define LG2_EPS -23.253496664211536f

// smem layout (bytes): E0[9216] E1[9216] ADJ0[17408] ADJ1[17408] = 53248
#define ES_STRIDE 144
#define ES_BYTES  9216
#define ADJ_STRIDE 68
#define ADJ_BYTES (64*ADJ_STRIDE*4)
#define ADJ_OFF   (2*ES_BYTES)
#define SMEM_G (ADJ_OFF + 2*ADJ_BYTES)   // 53248

// ---------------- device scratch ----------------
__device__ __nv_bfloat16 g_eB[(size_t)NJ_PAD*64];
__device__ __nv_bfloat16 g_aBF[B*64];
__device__ float    g_acc[B*4];
__device__ unsigned g_minL[B];
__device__ unsigned g_ctr;

// ---------------- helpers ----------------
__device__ __forceinline__ float ex2f_(float x){ float r; asm("ex2.approx.f32 %0, %1;" : "=f"(r) : "f"(x)); return r; }
__device__ __forceinline__ float lg2f_(float x){ float r; asm("lg2.approx.f32 %0, %1;" : "=f"(r) : "f"(x)); return r; }
__device__ __forceinline__ uint32_t smem_u32(const void* p){
    uint32_t a; asm("{ .reg .u64 t; cvta.to.shared.u64 t, %1; cvt.u32.u64 %0, t; }" : "=r"(a) : "l"(p)); return a; }
__device__ __forceinline__ unsigned ford(float f){
    int i = __float_as_int(f);
    return (i >= 0) ? ((unsigned)i | 0x80000000u) : ~(unsigned)i;
}
__device__ __forceinline__ float forddec(unsigned u){
    int i = (u & 0x80000000u) ? (int)(u & 0x7FFFFFFFu) : ~(int)u;
    return __int_as_float(i);
}
__device__ __forceinline__ void mma16816(float* c, const uint32_t* a, uint32_t b0, uint32_t b1){
    asm volatile("mma.sync.aligned.m16n8k16.row.col.f32.bf16.bf16.f32 "
        "{%0,%1,%2,%3}, {%4,%5,%6,%7}, {%8,%9}, {%0,%1,%2,%3};"
        : "+f"(c[0]), "+f"(c[1]), "+f"(c[2]), "+f"(c[3])
        : "r"(a[0]), "r"(a[1]), "r"(a[2]), "r"(a[3]), "r"(b0), "r"(b1));
}
#define LDM4(r0,r1,r2,r3,addr) \
    asm volatile("ldmatrix.sync.aligned.m8n8.x4.shared.b16 {%0,%1,%2,%3}, [%4];" \
        : "=r"(r0), "=r"(r1), "=r"(r2), "=r"(r3) : "r"(addr))

__device__ __forceinline__ void upd(float L, float y, float& z, float& t1, float& t2, float& t3, float& mn){
    y = fmaxf(y, KL_EPS);
    z += ex2f_(L);
    t1 = fmaf(y, L, t1);
    t2 += y;
    t3 = fmaf(y, lg2f_(y), t3);
    mn = fminf(mn, L);
}

// ---------------- kernel 0: fused normalize-E + init ----------------
__global__ void k_prep(const float* __restrict__ emb){
    if (blockIdx.x < 1596){
        int wid = threadIdx.x>>5, lane = threadIdx.x&31;
        int jb = (blockIdx.x*8 + wid)*4;
        float2 v[4]; float s[4];
#pragma unroll
        for(int r=0;r<4;r++){
            int j = jb + r;
            v[r] = make_float2(0.f, 0.f);
            if (j < NJ) v[r] = ((const float2*)emb)[(size_t)(j+1)*32 + lane];
            s[r] = v[r].x*v[r].x + v[r].y*v[r].y;
        }
#pragma unroll
        for(int o=16;o;o>>=1){
#pragma unroll
            for(int r=0;r<4;r++) s[r] += __shfl_xor_sync(0xffffffffu, s[r], o);
        }
#pragma unroll
        for(int r=0;r<4;r++){
            int j = jb + r;
            if (j < NJ_PAD){
                float inv = rsqrtf(fmaxf(s[r], 1e-12f));
                __nv_bfloat162 o2;
                o2.x = __float2bfloat16_rn(v[r].x*inv);
                o2.y = __float2bfloat16_rn(v[r].y*inv);
                ((__nv_bfloat162*)g_eB)[(size_t)j*32 + lane] = o2;
            }
        }
    } else {
        int i = (int)(blockIdx.x - 1596)*256 + threadIdx.x;   // 16 blocks -> 4096
        g_acc[i] = 0.f;
        if (i < B) g_minL[i] = 0xFFFFFFFFu;
        if (i == 0) g_ctr = 0u;
    }
}

// ---------------- kernel 1: gather + MLP + l2norm, fold t*log2e ----------------
__global__ void __launch_bounds__(256) k_mlp(const int* __restrict__ cards, const float* __restrict__ emb,
        const float* __restrict__ W1, const float* __restrict__ b1,
        const float* __restrict__ W2, const float* __restrict__ b2,
        const float* __restrict__ temp){
    extern __shared__ float dyn[];
    float* sW1 = dyn;
    float* sW2 = dyn + 16384;
    float* se  = dyn + 32768;
    float* sh  = dyn + 33280;
    float* so  = dyn + 35328;
    float* ssc = dyn + 35840;
    int t = threadIdx.x;
    int b0 = blockIdx.x*8;
    const float4* W1v = (const float4*)W1; float4* s1v = (float4*)sW1;
    const float4* W2v = (const float4*)W2; float4* s2v = (float4*)sW2;
#pragma unroll
    for(int i=0;i<16;i++) s1v[t + i*256] = W1v[t + i*256];
#pragma unroll
    for(int i=0;i<16;i++) s2v[t + i*256] = W2v[t + i*256];
#pragma unroll
    for(int i=0;i<2;i++){ int idx = t + i*256; int bi = idx>>6, k = idx&63;
        se[idx] = emb[(size_t)cards[b0+bi]*64 + k]; }
    __syncthreads();
    float bb1 = b1[t];
#pragma unroll
    for(int bi=0;bi<8;bi++){
        float h = bb1;
#pragma unroll
        for(int k=0;k<64;k++) h = fmaf(se[bi*64+k], sW1[k*256+t], h);
        sh[bi*256+t] = fmaxf(h, 0.f);
    }
    __syncthreads();
    int d = t&63, q = t>>6;
    float bb2 = b2[d];
#pragma unroll
    for(int r=0;r<2;r++){
        int bi = q*2 + r;
        float o = bb2;
#pragma unroll 8
        for(int j=0;j<256;j++) o = fmaf(sh[bi*256+j], sW2[j*64+d], o);
        so[bi*64+d] = o;
    }
    __syncthreads();
    if (t < 8){
        float s = 0.f;
#pragma unroll
        for(int dd=0;dd<64;dd++){ float v = so[t*64+dd]; s = fmaf(v, v, s); }
        ssc[t] = temp[0]*LOG2E*rsqrtf(fmaxf(s, 1e-12f));
    }
    __syncthreads();
#pragma unroll
    for(int i=0;i<2;i++){ int idx = t + i*256; int bi = idx>>6;
        g_aBF[(size_t)b0*64 + idx] = __float2bfloat16_rn(so[idx]*ssc[bi]); }
}

// ---------------- staging (chunk-major, hoisted offsets) ----------------
struct Stage {
    uint32_t offE[2];
    uint32_t dstE[2];
    uint32_t offA[5];
    uint32_t dstA[5];
    uint32_t nA;
};

template<bool SAFE>
__device__ __forceinline__ void stage_issue(Stage& st, int buf, uint32_t smbase,
                                            const char* __restrict__ adjB){
    uint32_t eb = smbase + buf*ES_BYTES;
    const char* eB = (const char*)g_eB;
#pragma unroll
    for(int i=0;i<2;i++){
        asm volatile("cp.async.cg.shared.global [%0], [%1], 16;"
                     :: "r"(eb + st.dstE[i]), "l"(eB + st.offE[i]));
        st.offE[i] += 8192;
    }
    uint32_t ab = smbase + ADJ_OFF + buf*ADJ_BYTES;
#pragma unroll
    for(int i=0;i<5;i++){
        if (i < (int)st.nA){
            uint32_t o = st.offA[i];
            uint32_t d = ab + st.dstA[i];
            if (SAFE || o + 16 <= NTOT4){
                asm volatile("cp.async.cg.shared.global [%0], [%1], 16;"
                             :: "r"(d), "l"(adjB + o));
            } else {
#pragma unroll
                for(int e=0;e<4;e++){
                    float v = 0.f;
                    if (o + e*4 + 4 <= NTOT4) v = __ldcs((const float*)(adjB + o + e*4));
                    asm volatile("st.shared.f32 [%0], %1;" :: "r"(d + e*4), "f"(v));
                }
            }
            st.offA[i] += 256;
        }
    }
    asm volatile("cp.async.commit_group;" ::: "memory");
}

// ---------------- kernel 2: HMMA GEMM + fused stats + last-CTA finalize (incl. inline fixup) ----------------
__global__ void __launch_bounds__(256, 4) k_gemm9(const float* __restrict__ adj,
                                                  const float* __restrict__ temp,
                                                  float* __restrict__ out){
    extern __shared__ __align__(16) char sm9[];
    const uint32_t smbase = smem_u32(sm9);
    int tid = threadIdx.x;
    int wid = tid>>5, lane = tid&31, g = lane>>2, tg = lane&3;
    int wr = wid&3, wc = wid>>2;
    int jc = blockIdx.x, rt = blockIdx.y;
    int jstart = jc*CHUNK;

    int r0l = wr*16 + g;
    int r0g = rt*64 + r0l;

    uint32_t A[4][4];
    {
        const uint32_t* a0 = (const uint32_t*)(g_aBF + (size_t)r0g*64);
        const uint32_t* a1 = (const uint32_t*)(g_aBF + (size_t)(r0g+8)*64);
#pragma unroll
        for(int kt=0;kt<4;kt++){
            A[kt][0]=a0[kt*8+tg];   A[kt][1]=a1[kt*8+tg];
            A[kt][2]=a0[kt*8+tg+4]; A[kt][3]=a1[kt*8+tg+4];
        }
    }
    const int ash = (int)(((size_t)r0g*NJ + (unsigned)jstart) & 3);
    const uint32_t lmo = (uint32_t)((wc*32 + (lane&7))*ES_STRIDE + (lane>>3)*16);
    const char* adjB = (const char*)adj;

    Stage st;
#pragma unroll
    for(int i=0;i<2;i++){
        int c = tid + i*256;
        int row = c>>3, seg = c&7;
        st.offE[i] = (uint32_t)(jstart + row)*128u + seg*16u;
        st.dstE[i] = (uint32_t)row*ES_STRIDE + seg*16u;
    }
    {
        int n = 0;
#pragma unroll
        for(int i=0;i<5;i++){
            int idx = tid + i*256;
            if (idx < 1088){
                int row = idx/17, ch = idx - row*17;
                size_t base = (size_t)(rt*64 + row)*NJ + (unsigned)jstart;
                st.offA[n] = (uint32_t)((base & ~(size_t)3)*4) + (uint32_t)ch*16u;
                st.dstA[n] = (uint32_t)row*(ADJ_STRIDE*4) + (uint32_t)ch*16u;
                n++;
            }
        }
        st.nA = (uint32_t)n;
    }

    float Z[2]={0.f,0.f}, T1[2]={0.f,0.f}, T2[2]={0.f,0.f}, T3[2]={0.f,0.f};
    float MN = 1e30f;

    if (jc != JC-1){
        // ======== fast path: 21 full tiles, unguarded staging ========
        stage_issue<true>(st, 0, smbase, adjB);
#pragma unroll 1
        for(int t=0;t<TILES;t++){
            if (t < TILES-1){
                stage_issue<true>(st, (t+1)&1, smbase, adjB);
                asm volatile("cp.async.wait_group 1;" ::: "memory");
            } else {
                asm volatile("cp.async.wait_group 0;" ::: "memory");
            }
            __syncthreads();

            uint32_t esb = smbase + (t&1)*ES_BYTES + lmo;
            const float* srow0 = (const float*)(sm9 + ADJ_OFF + (t&1)*ADJ_BYTES) + r0l*ADJ_STRIDE + ash;
            const float* srow1 = srow0 + 8*ADJ_STRIDE;

#pragma unroll
            for(int nt=0;nt<4;nt++){
                float acc[4] = {0.f, 0.f, 0.f, 0.f};
                uint32_t ad = esb + nt*(8*ES_STRIDE);
                uint32_t b00,b01,b10,b11,b20,b21,b30,b31;
                LDM4(b00,b01,b10,b11, ad);
                LDM4(b20,b21,b30,b31, ad + 64);
                mma16816(acc, A[0], b00, b01);
                mma16816(acc, A[1], b10, b11);
                mma16816(acc, A[2], b20, b21);
                mma16816(acc, A[3], b30, b31);
                int c = wc*32 + nt*8 + tg*2;
                upd(acc[0], srow0[c],   Z[0],T1[0],T2[0],T3[0],MN);
                upd(acc[1], srow0[c+1], Z[0],T1[0],T2[0],T3[0],MN);
                upd(acc[2], srow1[c],   Z[1],T1[1],T2[1],T3[1],MN);
                upd(acc[3], srow1[c+1], Z[1],T1[1],T2[1],T3[1],MN);
            }
            __syncthreads();
        }
    } else {
        // ======== general path: last chunk (271 cols, 5 tiles); guarded only for rt==15 ========
        int nvalid = NJ - jstart;
        int ntiles = (nvalid + 63)>>6;
        bool safe = (rt != 15);
        if (safe) stage_issue<true>(st, 0, smbase, adjB);
        else      stage_issue<false>(st, 0, smbase, adjB);
#pragma unroll 1
        for(int t=0;t<ntiles;t++){
            int j0 = jstart + (t<<6);
            int jv = NJ - j0; if (jv > 64) jv = 64;
            if (t < ntiles-1){
                if (safe) stage_issue<true>(st, (t+1)&1, smbase, adjB);
                else      stage_issue<false>(st, (t+1)&1, smbase, adjB);
                asm volatile("cp.async.wait_group 1;" ::: "memory");
            } else {
                asm volatile("cp.async.wait_group 0;" ::: "memory");
            }
            __syncthreads();

            uint32_t esb = smbase + (t&1)*ES_BYTES + lmo;
            const float* srow0 = (const float*)(sm9 + ADJ_OFF + (t&1)*ADJ_BYTES) + r0l*ADJ_STRIDE + ash;
            const float* srow1 = srow0 + 8*ADJ_STRIDE;

#pragma unroll
            for(int nt=0;nt<4;nt++){
                float acc[4] = {0.f, 0.f, 0.f, 0.f};
                uint32_t ad = esb + nt*(8*ES_STRIDE);
                uint32_t b00,b01,b10,b11,b20,b21,b30,b31;
                LDM4(b00,b01,b10,b11, ad);
                LDM4(b20,b21,b30,b31, ad + 64);
                mma16816(acc, A[0], b00, b01);
                mma16816(acc, A[1], b10, b11);
                mma16816(acc, A[2], b20, b21);
                mma16816(acc, A[3], b30, b31);
                int c = wc*32 + nt*8 + tg*2;
                if (c < jv){
                    upd(acc[0], srow0[c], Z[0],T1[0],T2[0],T3[0],MN);
                    upd(acc[2], srow1[c], Z[1],T1[1],T2[1],T3[1],MN);
                    if (c + 1 < jv){
                        upd(acc[1], srow0[c+1], Z[0],T1[0],T2[0],T3[0],MN);
                        upd(acc[3], srow1[c+1], Z[1],T1[1],T2[1],T3[1],MN);
                    }
                }
            }
            __syncthreads();
        }
    }

    // reduce over tg lanes, atomic merge
#pragma unroll
    for(int r=0;r<2;r++){
#pragma unroll
        for(int off=1; off<4; off<<=1){
            Z[r]  += __shfl_xor_sync(0xffffffffu, Z[r],  off);
            T1[r] += __shfl_xor_sync(0xffffffffu, T1[r], off);
            T2[r] += __shfl_xor_sync(0xffffffffu, T2[r], off);
            T3[r] += __shfl_xor_sync(0xffffffffu, T3[r], off);
        }
    }
#pragma unroll
    for(int off=1; off<4; off<<=1)
        MN = fminf(MN, __shfl_xor_sync(0xffffffffu, MN, off));
    if (tg == 0){
        unsigned mnu = ford(MN);
#pragma unroll
        for(int r=0;r<2;r++){
            int row = r0g + r*8;
            atomicAdd(&g_acc[row*4+0], Z[r]);
            atomicAdd(&g_acc[row*4+1], T1[r]);
            atomicAdd(&g_acc[row*4+2], T2[r]);
            atomicAdd(&g_acc[row*4+3], T3[r]);
            atomicMin(&g_minL[row], mnu);
        }
    }

    // ---- last CTA finalizes (incl. inline exact-clip fixup, expected no-op) ----
    __threadfence();
    __shared__ unsigned s_last;
    if (tid == 0) s_last = (atomicAdd(&g_ctr, 1u) == NCTA-1) ? 1u : 0u;
    __syncthreads();
    if (!s_last) return;

    float* t3s = (float*)sm9;               // [1024]
    float* crs = t3s + 1024;                // [1024]
    float* ls2 = crs + 1024;                // [1024]
    float* red = ls2 + 1024;                // [256]
    float* aa  = red + 256;                 // [64]
    __shared__ unsigned fl[32];
    __shared__ int s_any;
    if (tid < 32) fl[tid] = 0u;
    if (tid == 0) s_any = 0;
    __syncthreads();

    float T = temp[0];
#pragma unroll
    for(int i=0;i<4;i++){
        int b = tid + i*256;
        float Zb, T1b, T2b, T3b; unsigned mu;
        asm("ld.global.cg.f32 %0, [%1];" : "=f"(Zb)  : "l"(&g_acc[b*4+0]));
        asm("ld.global.cg.f32 %0, [%1];" : "=f"(T1b) : "l"(&g_acc[b*4+1]));
        asm("ld.global.cg.f32 %0, [%1];" : "=f"(T2b) : "l"(&g_acc[b*4+2]));
        asm("ld.global.cg.f32 %0, [%1];" : "=f"(T3b) : "l"(&g_acc[b*4+3]));
        asm("ld.global.cg.u32 %0, [%1];" : "=r"(mu)  : "l"(&g_minL[b]));
        float lse2 = lg2f_(Zb);
        float cross = T1b - lse2*T2b;
        t3s[b] = T3b; crs[b] = cross; ls2[b] = lse2;
        if (forddec(mu) - lse2 < LG2_EPS + 0.02f){
            atomicOr(&fl[b>>5], 1u<<(b&31));
            s_any = 1;
        }
    }
    __syncthreads();

    if (s_any){   // cold path: exact clipped recompute per flagged row
        for(int b=0;b<B;b++){
            if (!((fl[b>>5]>>(b&31)) & 1u)) continue;
            if (tid < 64) aa[tid] = __bfloat162float(g_aBF[b*64 + tid]);
            __syncthreads();
            float lse2 = ls2[b];
            float cr = 0.f;
            for(int j=tid; j<NJ; j+=256){
                float L = 0.f;
#pragma unroll
                for(int k=0;k<64;k++) L = fmaf(aa[k], __bfloat162float(g_eB[(size_t)j*64 + k]), L);
                float y = fmaxf(adj[(size_t)b*NJ + j], KL_EPS);
                cr = fmaf(y, fmaxf(L - lse2, LG2_EPS), cr);
            }
            red[tid] = cr; __syncthreads();
            for(int s=128;s;s>>=1){ if (tid < s) red[tid] += red[tid+s]; __syncthreads(); }
            if (tid == 0) crs[b] = red[0];
            __syncthreads();
        }
    }

    float local = 0.f;
#pragma unroll
    for(int i=0;i<4;i++){ int b = tid + i*256; local += t3s[b] - crs[b]; }
    red[tid] = local;
    __syncthreads();
    for(int s=128;s;s>>=1){ if (tid < s) red[tid] += red[tid+s]; __syncthreads(); }
    if (tid == 0) out[0] = red[0]*(1.0f/(float)B) + T*T*0.01f;
}

// ---------------- launch ----------------
extern "C" void kernel_launch(void* const* d_in, const int* in_sizes, int n_in,
                              void* d_out, int out_size){
    const int*   cards = (const int*)  d_in[0];
    const float* adj   = (const float*)d_in[1];
    const float* emb   = (const float*)d_in[2];
    const float* W1    = (const float*)d_in[3];
    const float* b1    = (const float*)d_in[4];
    const float* W2    = (const float*)d_in[5];
    const float* b2    = (const float*)d_in[6];
    const float* temp  = (const float*)d_in[7];

    cudaFuncSetAttribute(k_mlp,   cudaFuncAttributeMaxDynamicSharedMemorySize, 143392);
    cudaFuncSetAttribute(k_gemm9, cudaFuncAttributeMaxDynamicSharedMemorySize, SMEM_G);

    k_prep<<<1612, 256>>>(emb);                                    // idx 0 (enorm + init)
    k_mlp<<<128, 256, 143392>>>(cards, emb, W1, b1, W2, b2, temp); // idx 1
    k_gemm9<<<dim3(JC, 16), 256, SMEM_G>>>(adj, temp, (float*)d_out); // idx 2
}